// round 9
// baseline (speedup 1.0000x reference)
#include <cuda_runtime.h>
#include <cuda_bf16.h>
#include <cstdint>

#define kB 2
#define kS 2048
#define kD 1024
#define kH 16
#define kDK 64
#define kBH 32
#define kNB 4095
#define kM 4096
#define kOUT0 4194304LL
#define kROWS (kBH * kS)          // 65536 attn rows
#define SA 88                     // smem row stride (bf16): 176B, ldmatrix conflict-free

// ---------------- device scratch ----------------
__device__ __nv_bfloat16 g_xhi[kM*kD], g_xlo[kM*kD];
__device__ __nv_bfloat16 g_wqhi[kD*kD], g_wqlo[kD*kD];
__device__ __nv_bfloat16 g_wkhi[kD*kD], g_wklo[kD*kD];
__device__ __nv_bfloat16 g_wvhi[kD*kD], g_wvlo[kD*kD];
__device__ __nv_bfloat16 g_wohi[kD*kD], g_wolo[kD*kD];
__device__ __nv_bfloat16 g_qhi[kM*kD],  g_qlo[kM*kD];
__device__ __nv_bfloat16 g_khi[kM*kD],  g_klo[kM*kD];
__device__ __nv_bfloat16 g_vhi[kM*kD],  g_vlo[kM*kD];
__device__ __nv_bfloat16 g_vthi[kBH*kDK*kS], g_vtlo[kBH*kDK*kS];
__device__ __nv_bfloat16 g_chi[kM*kD],  g_clo[kM*kD];
__device__ float g_bias[kH*kNB];
__device__ float g_pmax[kROWS*16], g_psum[kROWS*16];
__device__ float g_rm[kROWS], g_rinv[kROWS];

// ---------------- PTX helpers ----------------
__device__ __forceinline__ uint32_t smem_u32(const void* p){
    uint32_t a;
    asm("{ .reg .u64 t; cvta.to.shared.u64 t, %1; cvt.u32.u64 %0, t; }" : "=r"(a) : "l"(p));
    return a;
}
__device__ __forceinline__ void ldsm4(uint32_t* r, uint32_t addr){
    asm volatile("ldmatrix.sync.aligned.m8n8.x4.shared.b16 {%0,%1,%2,%3}, [%4];"
        : "=r"(r[0]),"=r"(r[1]),"=r"(r[2]),"=r"(r[3]) : "r"(addr));
}
__device__ __forceinline__ void mma16816(float* c, const uint32_t* a, const uint32_t* b){
    asm volatile("mma.sync.aligned.m16n8k16.row.col.f32.bf16.bf16.f32 "
        "{%0,%1,%2,%3}, {%4,%5,%6,%7}, {%8,%9}, {%0,%1,%2,%3};"
        : "+f"(c[0]),"+f"(c[1]),"+f"(c[2]),"+f"(c[3])
        : "r"(a[0]),"r"(a[1]),"r"(a[2]),"r"(a[3]), "r"(b[0]),"r"(b[1]));
}
__device__ __forceinline__ void cp16(uint32_t dst, const void* src){
    asm volatile("cp.async.cg.shared.global [%0], [%1], 16;" :: "r"(dst), "l"(src));
}
__device__ __forceinline__ void cp_commit(){ asm volatile("cp.async.commit_group;" ::: "memory"); }
template<int N> __device__ __forceinline__ void cp_wait(){
    asm volatile("cp.async.wait_group %0;" :: "n"(N) : "memory");
}

// ---------------- small prep kernels ----------------
__global__ void bias_kernel(const float* __restrict__ rel_bias){
    int idx = blockIdx.x*blockDim.x + threadIdx.x;
    if (idx >= kH*kNB) return;
    int h = idx / kNB;
    int delta = idx % kNB - (kS-1);
    int bucket = (delta > 0) ? 16 : 0;
    int a = delta < 0 ? -delta : delta;
    int add;
    if      (a < 8)  add = a;
    else if (a < 12) add = 8;
    else if (a < 16) add = 9;
    else if (a < 23) add = 10;
    else if (a < 32) add = 11;
    else if (a < 46) add = 12;
    else if (a < 64) add = 13;
    else if (a < 91) add = 14;
    else             add = 15;
    g_bias[idx] = rel_bias[(bucket + add)*kH + h];
}

__global__ void convert_x_kernel(const float* __restrict__ x){
    int i = blockIdx.x*256 + threadIdx.x;
    float v = x[i];
    __nv_bfloat16 h = __float2bfloat16(v);
    g_xhi[i] = h;
    g_xlo[i] = __float2bfloat16(v - __bfloat162float(h));
}

__global__ void transpose_split_kernel(const float* __restrict__ W,
                                       __nv_bfloat16* __restrict__ Thi,
                                       __nv_bfloat16* __restrict__ Tlo){
    __shared__ float t[32][33];
    int x = blockIdx.x*32 + threadIdx.x;
    int y0 = blockIdx.y*32;
#pragma unroll
    for (int j = 0; j < 32; j += 8)
        t[threadIdx.y+j][threadIdx.x] = W[(size_t)(y0+threadIdx.y+j)*kD + x];
    __syncthreads();
    int n0 = blockIdx.x*32;
#pragma unroll
    for (int j = 0; j < 32; j += 8){
        float v = t[threadIdx.x][threadIdx.y+j];
        size_t o = (size_t)(n0+threadIdx.y+j)*kD + y0 + threadIdx.x;
        __nv_bfloat16 h = __float2bfloat16(v);
        Thi[o] = h;
        Tlo[o] = __float2bfloat16(v - __bfloat162float(h));
    }
}

__global__ void transpose_v_kernel(){
    __shared__ __nv_bfloat16 th[32][33], tl[32][33];
    int bh = blockIdx.z, b = bh >> 4, h = bh & 15;
    int s0 = blockIdx.x*32, d0 = blockIdx.y*32;
#pragma unroll
    for (int j = 0; j < 32; j += 8){
        size_t src = (size_t)(b*kS + s0 + threadIdx.y + j)*kD + h*kDK + d0 + threadIdx.x;
        th[threadIdx.y+j][threadIdx.x] = g_vhi[src];
        tl[threadIdx.y+j][threadIdx.x] = g_vlo[src];
    }
    __syncthreads();
#pragma unroll
    for (int j = 0; j < 32; j += 8){
        size_t dst = ((size_t)bh*kDK + d0 + threadIdx.y + j)*kS + s0 + threadIdx.x;
        g_vthi[dst] = th[threadIdx.x][threadIdx.y+j];
        g_vtlo[dst] = tl[threadIdx.x][threadIdx.y+j];
    }
}

// fold 16 per-block partials into per-row (max, 1/sum)
__global__ void reduce_stats_kernel(){
    int row = blockIdx.x*256 + threadIdx.x;
    float4 m4[4], s4[4];
#pragma unroll
    for (int i = 0; i < 4; i++){
        m4[i] = *(const float4*)&g_pmax[(size_t)row*16 + i*4];
        s4[i] = *(const float4*)&g_psum[(size_t)row*16 + i*4];
    }
    float M = -3.0e38f;
#pragma unroll
    for (int i = 0; i < 4; i++)
        M = fmaxf(M, fmaxf(fmaxf(m4[i].x, m4[i].y), fmaxf(m4[i].z, m4[i].w)));
    float S = 0.0f;
#pragma unroll
    for (int i = 0; i < 4; i++){
        S += s4[i].x*__expf(m4[i].x - M) + s4[i].y*__expf(m4[i].y - M)
           + s4[i].z*__expf(m4[i].z - M) + s4[i].w*__expf(m4[i].w - M);
    }
    g_rm[row]   = M;
    g_rinv[row] = 1.0f / S;
}

// ---------------------------------------------------------------------------
// bf16x3 GEMM via mma.sync, 512 threads.  BM=128, BK=64.
// ASPLIT: A = raw fp32 logits; staging applies softmax (g_rm/g_rinv), writes
//         normalized attn back to gmem, splits to bf16 hi/lo.
// OUTMODE: 0 fp32 | 1 fp32+bias, emit per-row partial (max, sumexp) | 2 bf16 pair
// ---------------------------------------------------------------------------
template<int BN, bool ASPLIT, int OUTMODE>
__global__ void __launch_bounds__(512, 1) gemm3_kernel(
    const __nv_bfloat16* __restrict__ Ahi_g, const __nv_bfloat16* __restrict__ Alo_g,
    const float* __restrict__ Af_g, float* __restrict__ Aout_g,
    int lda, long long sAb, long long sAh,
    const __nv_bfloat16* __restrict__ Bhi_g, const __nv_bfloat16* __restrict__ Blo_g,
    int ldb, long long sBb, long long sBh,
    float* __restrict__ Cf, __nv_bfloat16* __restrict__ Chi, __nv_bfloat16* __restrict__ Clo,
    int ldc, long long sCb, long long sCh, int K)
{
    extern __shared__ char smem[];
    __shared__ float bias_sm[256];

    const int tid = threadIdx.x, wid = tid >> 5, lane = tid & 31;
    const int zb = blockIdx.z >> 4, zh = blockIdx.z & 15;
    const int m0 = blockIdx.y * 128, n0 = blockIdx.x * BN;

    constexpr int A_BYTES = 128 * SA * 2;
    constexpr int B_BYTES = BN * SA * 2;
    constexpr int STAGE   = 2*A_BYTES + 2*B_BYTES;
    const uint32_t smb = smem_u32(smem);

    if (OUTMODE == 1 && tid < 255)
        bias_sm[tid] = g_bias[zh*kNB + n0 - m0 + 1920 + tid];

    const __nv_bfloat16* Ah = Ahi_g + zb*sAb + zh*sAh;
    const __nv_bfloat16* Al = Alo_g + zb*sAb + zh*sAh;
    const float*         Af = Af_g  ? Af_g  + zb*sAb + zh*sAh : nullptr;
    float*               Ao = Aout_g? Aout_g+ zb*sAb + zh*sAh : nullptr;
    const __nv_bfloat16* Bh = Bhi_g + zb*sBb + zh*sBh;
    const __nv_bfloat16* Bl = Blo_g + zb*sBb + zh*sBh;

    const int T = K >> 6;

    auto issue = [&](int t){
        const int s = t & 1, k0 = t << 6;
        const uint32_t stA_hi = smb + s*STAGE;
        const uint32_t stA_lo = stA_hi + A_BYTES;
        const uint32_t stB_hi = stA_hi + 2*A_BYTES;
        const uint32_t stB_lo = stB_hi + B_BYTES;
        if (!ASPLIT){
#pragma unroll
            for (int i = 0; i < 2; i++){
                int u = i*512 + tid, row = u >> 3, c = u & 7;
                size_t so = (size_t)(m0+row)*lda + k0 + c*8;
                uint32_t off = (uint32_t)(row*(SA*2) + c*16);
                cp16(stA_hi + off, Ah + so);
                cp16(stA_lo + off, Al + so);
            }
        } else {
#pragma unroll
            for (int i = 0; i < 4; i++){
                int u = i*512 + tid, row = u >> 4, c4 = u & 15;
                size_t so = (size_t)(m0+row)*lda + k0 + c4*4;
                float4 v = *(const float4*)(Af + so);
                float M = g_rm[(size_t)blockIdx.z*kS + m0 + row];
                float I = g_rinv[(size_t)blockIdx.z*kS + m0 + row];
                v.x = __expf(v.x - M)*I; v.y = __expf(v.y - M)*I;
                v.z = __expf(v.z - M)*I; v.w = __expf(v.w - M)*I;
                *(float4*)(Ao + so) = v;               // final normalized attn
                __nv_bfloat162 h0 = __floats2bfloat162_rn(v.x, v.y);
                __nv_bfloat162 h1 = __floats2bfloat162_rn(v.z, v.w);
                __nv_bfloat162 l0 = __floats2bfloat162_rn(v.x - __bfloat162float(h0.x),
                                                          v.y - __bfloat162float(h0.y));
                __nv_bfloat162 l1 = __floats2bfloat162_rn(v.z - __bfloat162float(h1.x),
                                                          v.w - __bfloat162float(h1.y));
                uint32_t off = (uint32_t)(row*(SA*2) + c4*8);
                asm volatile("st.shared.v2.b32 [%0], {%1,%2};"
                             :: "r"(stA_hi + off), "r"(*(uint32_t*)&h0), "r"(*(uint32_t*)&h1) : "memory");
                asm volatile("st.shared.v2.b32 [%0], {%1,%2};"
                             :: "r"(stA_lo + off), "r"(*(uint32_t*)&l0), "r"(*(uint32_t*)&l1) : "memory");
            }
        }
#pragma unroll
        for (int i = 0; i < (BN == 128 ? 2 : 1); i++){
            int u = i*512 + tid, row = u >> 3, c = u & 7;
            size_t so = (size_t)(n0+row)*ldb + k0 + c*8;
            uint32_t off = (uint32_t)(row*(SA*2) + c*16);
            cp16(stB_hi + off, Bh + so);
            cp16(stB_lo + off, Bl + so);
        }
    };

    // warp grid: BN=128 -> 4n x 4m (warp tile 32x32); BN=64 -> 2n x 8m (16x32)
    constexpr int MF = (BN == 128) ? 2 : 1;
    const int wm = (BN == 128) ? (wid >> 2)*32 : (wid >> 1)*16;
    const int wn = (BN == 128) ? (wid & 3)*32  : (wid & 1)*32;

    const uint32_t a_off = (uint32_t)((wm + (lane & 15))*(SA*2) + (lane >> 4)*16);
    const uint32_t b_off = (uint32_t)((wn + ((lane >> 4) << 3) + (lane & 7))*(SA*2)
                                      + ((lane >> 3) & 1)*16);
    float acc[MF][4][4];
#pragma unroll
    for (int i = 0; i < MF; i++)
#pragma unroll
        for (int j = 0; j < 4; j++)
#pragma unroll
            for (int e = 0; e < 4; e++) acc[i][j][e] = 0.0f;

    issue(0);
    cp_commit();

    for (int t = 0; t < T; t++){
        if (t + 1 < T){ issue(t+1); cp_commit(); cp_wait<1>(); }
        else          { cp_wait<0>(); }
        __syncthreads();

        const int s = t & 1;
        const uint32_t stA_hi = smb + s*STAGE;
        const uint32_t stA_lo = stA_hi + A_BYTES;
        const uint32_t stB_hi = stA_hi + 2*A_BYTES;
        const uint32_t stB_lo = stB_hi + B_BYTES;

#pragma unroll
        for (int kk = 0; kk < 4; kk++){
            uint32_t ah[MF][4], al[MF][4], bh[2][4], bl[2][4];
            const uint32_t kb = kk*32;
#pragma unroll
            for (int i = 0; i < MF; i++){
                ldsm4(ah[i], stA_hi + a_off + i*16*(SA*2) + kb);
                ldsm4(al[i], stA_lo + a_off + i*16*(SA*2) + kb);
            }
#pragma unroll
            for (int j2 = 0; j2 < 2; j2++){
                ldsm4(bh[j2], stB_hi + b_off + j2*16*(SA*2) + kb);
                ldsm4(bl[j2], stB_lo + b_off + j2*16*(SA*2) + kb);
            }
#pragma unroll
            for (int i = 0; i < MF; i++)
#pragma unroll
                for (int j = 0; j < 4; j++){
                    const uint32_t* Bh2 = &bh[j >> 1][(j & 1)*2];
                    const uint32_t* Bl2 = &bl[j >> 1][(j & 1)*2];
                    mma16816(acc[i][j], ah[i], Bh2);
                    mma16816(acc[i][j], ah[i], Bl2);
                    mma16816(acc[i][j], al[i], Bh2);
                }
        }
        __syncthreads();
    }

    // ---- epilogue: regs -> swizzled fp32 smem tile -> coalesced stores ----
    float* ft = (float*)smem;
    const int q = lane >> 2, nn0 = (lane & 3)*2;
#pragma unroll
    for (int i = 0; i < MF; i++)
#pragma unroll
        for (int j = 0; j < 4; j++){
            int n = wn + j*8 + nn0;
            int C4 = n >> 2, half = (n >> 1) & 1;
            int r0 = wm + i*16 + q, r1 = r0 + 8;
            *(float2*)&ft[r0*BN + ((C4 ^ (r0 & 7)) << 2) + half*2] =
                make_float2(acc[i][j][0], acc[i][j][1]);
            *(float2*)&ft[r1*BN + ((C4 ^ (r1 & 7)) << 2) + half*2] =
                make_float2(acc[i][j][2], acc[i][j][3]);
        }
    __syncthreads();

    const long long offC = zb*sCb + zh*sCh;
    constexpr int RW = BN / 4;
    constexpr int ITER = 128 * RW / 512;
#pragma unroll
    for (int i = 0; i < ITER; i++){
        int u = i*512 + tid;
        int rr = u / RW, C4 = u % RW;
        int C4s = C4 ^ (rr & 7);
        float4 v = *(const float4*)&ft[rr*BN + C4s*4];
        const size_t co = (size_t)offC + (size_t)(m0+rr)*ldc + n0 + C4*4;
        if (OUTMODE == 0){
            *(float4*)(Cf + co) = v;
        } else if (OUTMODE == 1){
            int bi = C4*4 - rr + 127;
            v.x += bias_sm[bi];   v.y += bias_sm[bi+1];
            v.z += bias_sm[bi+2]; v.w += bias_sm[bi+3];
            *(float4*)(Cf + co) = v;                    // raw logits
            // per-row partial stats: lanes of this warp cover the whole row
            float M = fmaxf(fmaxf(v.x, v.y), fmaxf(v.z, v.w));
#pragma unroll
            for (int o = 16; o; o >>= 1) M = fmaxf(M, __shfl_xor_sync(~0u, M, o));
            float S = __expf(v.x - M) + __expf(v.y - M) + __expf(v.z - M) + __expf(v.w - M);
#pragma unroll
            for (int o = 16; o; o >>= 1) S += __shfl_xor_sync(~0u, S, o);
            if (lane == 0){
                size_t pi = ((size_t)blockIdx.z*kS + m0 + rr)*16 + blockIdx.x;
                g_pmax[pi] = M;
                g_psum[pi] = S;
            }
        } else {
            __nv_bfloat162 h0 = __floats2bfloat162_rn(v.x, v.y);
            __nv_bfloat162 h1 = __floats2bfloat162_rn(v.z, v.w);
            __nv_bfloat162 l0 = __floats2bfloat162_rn(v.x - __bfloat162float(h0.x),
                                                      v.y - __bfloat162float(h0.y));
            __nv_bfloat162 l1 = __floats2bfloat162_rn(v.z - __bfloat162float(h1.x),
                                                      v.w - __bfloat162float(h1.y));
            *(uint2*)(Chi + co) = make_uint2(*(uint32_t*)&h0, *(uint32_t*)&h1);
            *(uint2*)(Clo + co) = make_uint2(*(uint32_t*)&l0, *(uint32_t*)&l1);
        }
    }
}

// ---------------------------------------------------------------------------
extern "C" void kernel_launch(void* const* d_in, const int* in_sizes, int n_in,
                              void* d_out, int out_size) {
    const float* hidden = (const float*)d_in[0];
    const float* wq = (const float*)d_in[1];
    const float* wk = (const float*)d_in[2];
    const float* wv = (const float*)d_in[3];
    const float* wo = (const float*)d_in[4];
    const float* rb = (const float*)d_in[5];
    float* out  = (float*)d_out;
    float* attn = out + kOUT0;

    #define SYM(p, s) void* p; cudaGetSymbolAddress(&p, s)
    SYM(xhi, g_xhi); SYM(xlo, g_xlo);
    SYM(wqhi, g_wqhi); SYM(wqlo, g_wqlo);
    SYM(wkhi, g_wkhi); SYM(wklo, g_wklo);
    SYM(wvhi, g_wvhi); SYM(wvlo, g_wvlo);
    SYM(wohi, g_wohi); SYM(wolo, g_wolo);
    SYM(qhi, g_qhi); SYM(qlo, g_qlo);
    SYM(khi, g_khi); SYM(klo, g_klo);
    SYM(vhi, g_vhi); SYM(vlo, g_vlo);
    SYM(vthi, g_vthi); SYM(vtlo, g_vtlo);
    SYM(chi, g_chi); SYM(clo, g_clo);
    #undef SYM
    typedef const __nv_bfloat16* BF;
    typedef __nv_bfloat16* BFm;

    auto proj = gemm3_kernel<128, false, 2>;
    auto qkg  = gemm3_kernel<128, false, 1>;
    auto pvg  = gemm3_kernel<64,  true,  2>;
    auto outg = gemm3_kernel<128, false, 0>;
    cudaFuncSetAttribute(proj, cudaFuncAttributeMaxDynamicSharedMemorySize, 180224);
    cudaFuncSetAttribute(qkg,  cudaFuncAttributeMaxDynamicSharedMemorySize, 180224);
    cudaFuncSetAttribute(outg, cudaFuncAttributeMaxDynamicSharedMemorySize, 180224);
    cudaFuncSetAttribute(pvg,  cudaFuncAttributeMaxDynamicSharedMemorySize, 135168);

    bias_kernel<<<(kH*kNB + 255)/256, 256>>>(rb);
    convert_x_kernel<<<kM*kD/256, 256>>>(hidden);
    dim3 tb(32, 8);
    transpose_split_kernel<<<dim3(32, 32), tb>>>(wq, (BFm)wqhi, (BFm)wqlo);
    transpose_split_kernel<<<dim3(32, 32), tb>>>(wk, (BFm)wkhi, (BFm)wklo);
    transpose_split_kernel<<<dim3(32, 32), tb>>>(wv, (BFm)wvhi, (BFm)wvlo);
    transpose_split_kernel<<<dim3(32, 32), tb>>>(wo, (BFm)wohi, (BFm)wolo);

    proj<<<dim3(8, 32, 1), 512, 180224>>>(
        (BF)xhi, (BF)xlo, nullptr, nullptr, kD, 0, 0,
        (BF)wqhi, (BF)wqlo, kD, 0, 0,
        nullptr, (BFm)qhi, (BFm)qlo, kD, 0, 0, kD);
    proj<<<dim3(8, 32, 1), 512, 180224>>>(
        (BF)xhi, (BF)xlo, nullptr, nullptr, kD, 0, 0,
        (BF)wkhi, (BF)wklo, kD, 0, 0,
        nullptr, (BFm)khi, (BFm)klo, kD, 0, 0, kD);
    proj<<<dim3(8, 32, 1), 512, 180224>>>(
        (BF)xhi, (BF)xlo, nullptr, nullptr, kD, 0, 0,
        (BF)wvhi, (BF)wvlo, kD, 0, 0,
        nullptr, (BFm)vhi, (BFm)vlo, kD, 0, 0, kD);

    transpose_v_kernel<<<dim3(64, 2, 32), tb>>>();

    // raw logits + per-block row partials
    qkg<<<dim3(16, 16, 32), 512, 180224>>>(
        (BF)qhi, (BF)qlo, nullptr, nullptr, kD, 2097152LL, 64LL,
        (BF)khi, (BF)klo, kD, 2097152LL, 64LL,
        attn, nullptr, nullptr, kS, 67108864LL, 4194304LL, kDK);

    reduce_stats_kernel<<<kROWS/256, 256>>>();

    // PV: staging normalizes logits (writes final attn) + MMA with Vt
    pvg<<<dim3(1, 16, 32), 512, 135168>>>(
        nullptr, nullptr, attn, attn, kS, 67108864LL, 4194304LL,
        (BF)vthi, (BF)vtlo, kS, 2097152LL, 131072LL,
        nullptr, (BFm)chi, (BFm)clo, kD, 2097152LL, 64LL, kS);

    outg<<<dim3(8, 32, 1), 512, 180224>>>(
        (BF)chi, (BF)clo, nullptr, nullptr, kD, 0, 0,
        (BF)wohi, (BF)wolo, kD, 0, 0,
        out, nullptr, nullptr, kD, 0, 0, kD);
}

// round 12
// speedup vs baseline: 1.2107x; 1.2107x over previous
#include <cuda_runtime.h>
#include <cuda_bf16.h>
#include <cstdint>

#define kB 2
#define kS 2048
#define kD 1024
#define kH 16
#define kDK 64
#define kBH 32
#define kNB 4095
#define kM 4096
#define kOUT0 4194304LL
#define SA 40      // smem row stride in bf16 (80B: 16B-aligned, ldmatrix conflict-free)

// ---------------- device scratch ----------------
__device__ __nv_bfloat16 g_xhi[kM*kD], g_xlo[kM*kD];
__device__ __nv_bfloat16 g_wqhi[kD*kD], g_wqlo[kD*kD];
__device__ __nv_bfloat16 g_wkhi[kD*kD], g_wklo[kD*kD];
__device__ __nv_bfloat16 g_wvhi[kD*kD], g_wvlo[kD*kD];
__device__ __nv_bfloat16 g_wohi[kD*kD], g_wolo[kD*kD];
__device__ __nv_bfloat16 g_qhi[kM*kD],  g_qlo[kM*kD];
__device__ __nv_bfloat16 g_khi[kM*kD],  g_klo[kM*kD];
__device__ __nv_bfloat16 g_vhi[kM*kD],  g_vlo[kM*kD];
__device__ __nv_bfloat16 g_vthi[kBH*kDK*kS], g_vtlo[kBH*kDK*kS];
__device__ __nv_bfloat16 g_chi[kM*kD],  g_clo[kM*kD];
__device__ float g_bias[kH*kNB];

// ---------------- PTX helpers ----------------
__device__ __forceinline__ uint32_t smem_u32(const void* p){
    uint32_t a;
    asm("{ .reg .u64 t; cvta.to.shared.u64 t, %1; cvt.u32.u64 %0, t; }" : "=r"(a) : "l"(p));
    return a;
}
__device__ __forceinline__ void ldsm4(uint32_t* r, uint32_t addr){
    asm volatile("ldmatrix.sync.aligned.m8n8.x4.shared.b16 {%0,%1,%2,%3}, [%4];"
        : "=r"(r[0]),"=r"(r[1]),"=r"(r[2]),"=r"(r[3]) : "r"(addr));
}
__device__ __forceinline__ void mma16816(float* c, const uint32_t* a, const uint32_t* b){
    asm volatile("mma.sync.aligned.m16n8k16.row.col.f32.bf16.bf16.f32 "
        "{%0,%1,%2,%3}, {%4,%5,%6,%7}, {%8,%9}, {%0,%1,%2,%3};"
        : "+f"(c[0]),"+f"(c[1]),"+f"(c[2]),"+f"(c[3])
        : "r"(a[0]),"r"(a[1]),"r"(a[2]),"r"(a[3]), "r"(b[0]),"r"(b[1]));
}
__device__ __forceinline__ void cp16(uint32_t dst, const void* src){
    asm volatile("cp.async.cg.shared.global [%0], [%1], 16;" :: "r"(dst), "l"(src));
}
__device__ __forceinline__ void cp_commit(){ asm volatile("cp.async.commit_group;" ::: "memory"); }
template<int N> __device__ __forceinline__ void cp_wait(){
    asm volatile("cp.async.wait_group %0;" :: "n"(N) : "memory");
}

// ---------------- small prep kernels ----------------
__global__ void bias_kernel(const float* __restrict__ rel_bias){
    int idx = blockIdx.x*blockDim.x + threadIdx.x;
    if (idx >= kH*kNB) return;
    int h = idx / kNB;
    int delta = idx % kNB - (kS-1);
    int bucket = (delta > 0) ? 16 : 0;
    int a = delta < 0 ? -delta : delta;
    int add;
    if      (a < 8)  add = a;
    else if (a < 12) add = 8;
    else if (a < 16) add = 9;
    else if (a < 23) add = 10;
    else if (a < 32) add = 11;
    else if (a < 46) add = 12;
    else if (a < 64) add = 13;
    else if (a < 91) add = 14;
    else             add = 15;
    g_bias[idx] = rel_bias[(bucket + add)*kH + h];
}

__global__ void convert_x_kernel(const float* __restrict__ x){
    int i = blockIdx.x*256 + threadIdx.x;
    float v = x[i];
    __nv_bfloat16 h = __float2bfloat16(v);
    g_xhi[i] = h;
    g_xlo[i] = __float2bfloat16(v - __bfloat162float(h));
}

__global__ void transpose_split_kernel(const float* __restrict__ W,
                                       __nv_bfloat16* __restrict__ Thi,
                                       __nv_bfloat16* __restrict__ Tlo){
    __shared__ float t[32][33];
    int x = blockIdx.x*32 + threadIdx.x;
    int y0 = blockIdx.y*32;
#pragma unroll
    for (int j = 0; j < 32; j += 8)
        t[threadIdx.y+j][threadIdx.x] = W[(size_t)(y0+threadIdx.y+j)*kD + x];
    __syncthreads();
    int n0 = blockIdx.x*32;
#pragma unroll
    for (int j = 0; j < 32; j += 8){
        float v = t[threadIdx.x][threadIdx.y+j];
        size_t o = (size_t)(n0+threadIdx.y+j)*kD + y0 + threadIdx.x;
        __nv_bfloat16 h = __float2bfloat16(v);
        Thi[o] = h;
        Tlo[o] = __float2bfloat16(v - __bfloat162float(h));
    }
}

__global__ void transpose_v_kernel(){
    __shared__ __nv_bfloat16 th[32][33], tl[32][33];
    int bh = blockIdx.z, b = bh >> 4, h = bh & 15;
    int s0 = blockIdx.x*32, d0 = blockIdx.y*32;
#pragma unroll
    for (int j = 0; j < 32; j += 8){
        size_t src = (size_t)(b*kS + s0 + threadIdx.y + j)*kD + h*kDK + d0 + threadIdx.x;
        th[threadIdx.y+j][threadIdx.x] = g_vhi[src];
        tl[threadIdx.y+j][threadIdx.x] = g_vlo[src];
    }
    __syncthreads();
#pragma unroll
    for (int j = 0; j < 32; j += 8){
        size_t dst = ((size_t)bh*kDK + d0 + threadIdx.y + j)*kS + s0 + threadIdx.x;
        g_vthi[dst] = th[threadIdx.x][threadIdx.y+j];
        g_vtlo[dst] = tl[threadIdx.x][threadIdx.y+j];
    }
}

// ---------------- softmax over logit rows (in place) ----------------
__global__ void __launch_bounds__(256) softmax_kernel(float* __restrict__ attn){
    __shared__ float red[8];
    float* p = attn + (size_t)blockIdx.x * kS;
    int tid = threadIdx.x, wid = tid >> 5, lid = tid & 31;
    float4 v0 = ((const float4*)p)[tid];
    float4 v1 = ((const float4*)p)[tid + 256];
    float m = fmaxf(fmaxf(fmaxf(v0.x,v0.y), fmaxf(v0.z,v0.w)),
                    fmaxf(fmaxf(v1.x,v1.y), fmaxf(v1.z,v1.w)));
#pragma unroll
    for (int o = 16; o; o >>= 1) m = fmaxf(m, __shfl_xor_sync(~0u, m, o));
    if (lid == 0) red[wid] = m;
    __syncthreads();
    m = red[0];
#pragma unroll
    for (int i = 1; i < 8; i++) m = fmaxf(m, red[i]);
    v0.x = __expf(v0.x-m); v0.y = __expf(v0.y-m); v0.z = __expf(v0.z-m); v0.w = __expf(v0.w-m);
    v1.x = __expf(v1.x-m); v1.y = __expf(v1.y-m); v1.z = __expf(v1.z-m); v1.w = __expf(v1.w-m);
    float s = v0.x+v0.y+v0.z+v0.w + v1.x+v1.y+v1.z+v1.w;
#pragma unroll
    for (int o = 16; o; o >>= 1) s += __shfl_xor_sync(~0u, s, o);
    __syncthreads();
    if (lid == 0) red[wid] = s;
    __syncthreads();
    s = red[0];
#pragma unroll
    for (int i = 1; i < 8; i++) s += red[i];
    float inv = 1.0f / s;
    v0.x*=inv; v0.y*=inv; v0.z*=inv; v0.w*=inv;
    v1.x*=inv; v1.y*=inv; v1.z*=inv; v1.w*=inv;
    ((float4*)p)[tid] = v0;
    ((float4*)p)[tid + 256] = v1;
}

// ---------------------------------------------------------------------------
// bf16x3 GEMM via mma.sync, 256 threads, BM=128, BK=32 (2 CTA/SM).
// ---------------------------------------------------------------------------
template<int BN, bool ASPLIT, int OUTMODE>
__global__ void __launch_bounds__(256) gemm3_kernel(
    const __nv_bfloat16* __restrict__ Ahi_g, const __nv_bfloat16* __restrict__ Alo_g,
    const float* __restrict__ Af_g, int lda, long long sAb, long long sAh,
    const __nv_bfloat16* __restrict__ Bhi_g, const __nv_bfloat16* __restrict__ Blo_g,
    int ldb, long long sBb, long long sBh,
    float* __restrict__ Cf, __nv_bfloat16* __restrict__ Chi, __nv_bfloat16* __restrict__ Clo,
    int ldc, long long sCb, long long sCh, int K)
{
    extern __shared__ char smem[];
    __shared__ float bias_sm[256];

    const int tid = threadIdx.x, wid = tid >> 5, lane = tid & 31;
    const int zb = blockIdx.z >> 4, zh = blockIdx.z & 15;
    const int m0 = blockIdx.y * 128, n0 = blockIdx.x * BN;

    constexpr int A_BYTES = 128 * SA * 2;          // 10240
    constexpr int B_BYTES = BN * SA * 2;
    constexpr int STAGE   = 2*A_BYTES + 2*B_BYTES;
    const uint32_t smb = smem_u32(smem);

    if (OUTMODE == 1 && tid < 255)
        bias_sm[tid] = g_bias[zh*kNB + n0 - m0 + 1920 + tid];

    const __nv_bfloat16* Ah = Ahi_g + zb*sAb + zh*sAh;
    const __nv_bfloat16* Al = Alo_g + zb*sAb + zh*sAh;
    const float*         Af = Af_g ? Af_g + zb*sAb + zh*sAh : nullptr;
    const __nv_bfloat16* Bh = Bhi_g + zb*sBb + zh*sBh;
    const __nv_bfloat16* Bl = Blo_g + zb*sBb + zh*sBh;

    const int T = K >> 5;                          // BK = 32

    auto issue = [&](int t){
        const int s = t & 1, k0 = t << 5;
        const uint32_t stA_hi = smb + s*STAGE;
        const uint32_t stA_lo = stA_hi + A_BYTES;
        const uint32_t stB_hi = stA_hi + 2*A_BYTES;
        const uint32_t stB_lo = stB_hi + B_BYTES;
        if (!ASPLIT){
#pragma unroll
            for (int i = 0; i < 2; i++){
                int u = i*256 + tid, row = u >> 2, c = u & 3;
                size_t so = (size_t)(m0+row)*lda + k0 + c*8;
                uint32_t off = (uint32_t)(row*(SA*2) + c*16);
                cp16(stA_hi + off, Ah + so);
                cp16(stA_lo + off, Al + so);
            }
        } else {
#pragma unroll
            for (int i = 0; i < 4; i++){
                int u = i*256 + tid, row = u >> 3, c4 = u & 7;
                float4 v = *(const float4*)(Af + (size_t)(m0+row)*lda + k0 + c4*4);
                __nv_bfloat162 h0 = __floats2bfloat162_rn(v.x, v.y);
                __nv_bfloat162 h1 = __floats2bfloat162_rn(v.z, v.w);
                __nv_bfloat162 l0 = __floats2bfloat162_rn(v.x - __bfloat162float(h0.x),
                                                          v.y - __bfloat162float(h0.y));
                __nv_bfloat162 l1 = __floats2bfloat162_rn(v.z - __bfloat162float(h1.x),
                                                          v.w - __bfloat162float(h1.y));
                uint32_t off = (uint32_t)(row*(SA*2) + c4*8);
                asm volatile("st.shared.v2.b32 [%0], {%1,%2};"
                             :: "r"(stA_hi + off), "r"(*(uint32_t*)&h0), "r"(*(uint32_t*)&h1) : "memory");
                asm volatile("st.shared.v2.b32 [%0], {%1,%2};"
                             :: "r"(stA_lo + off), "r"(*(uint32_t*)&l0), "r"(*(uint32_t*)&l1) : "memory");
            }
        }
#pragma unroll
        for (int i = 0; i < (BN == 128 ? 2 : 1); i++){
            int u = i*256 + tid, row = u >> 2, c = u & 3;
            size_t so = (size_t)(n0+row)*ldb + k0 + c*8;
            uint32_t off = (uint32_t)(row*(SA*2) + c*16);
            cp16(stB_hi + off, Bh + so);
            cp16(stB_lo + off, Bl + so);
        }
    };

    // warp grid: 2m x 4n (BN=128, warp tile 64x32) / 4m x 2n (BN=64, 32x32)
    constexpr int MF = (BN == 128) ? 4 : 2;
    const int wm = (BN == 128) ? (wid >> 2)*64 : (wid >> 1)*32;
    const int wn = (BN == 128) ? (wid & 3)*32  : (wid & 1)*32;

    const uint32_t a_off = (uint32_t)((wm + (lane & 15))*(SA*2) + (lane >> 4)*16);
    const uint32_t b_off = (uint32_t)((wn + ((lane >> 4) << 3) + (lane & 7))*(SA*2)
                                      + ((lane >> 3) & 1)*16);
    float acc[MF][4][4];
#pragma unroll
    for (int i = 0; i < MF; i++)
#pragma unroll
        for (int j = 0; j < 4; j++)
#pragma unroll
            for (int e = 0; e < 4; e++) acc[i][j][e] = 0.0f;

    issue(0);
    cp_commit();

    for (int t = 0; t < T; t++){
        if (t + 1 < T){ issue(t+1); cp_commit(); cp_wait<1>(); }
        else          { cp_wait<0>(); }
        __syncthreads();

        const int s = t & 1;
        const uint32_t stA_hi = smb + s*STAGE;
        const uint32_t stA_lo = stA_hi + A_BYTES;
        const uint32_t stB_hi = stA_hi + 2*A_BYTES;
        const uint32_t stB_lo = stB_hi + B_BYTES;

#pragma unroll
        for (int kk = 0; kk < 2; kk++){
            uint32_t ah[MF][4], al[MF][4], bh[2][4], bl[2][4];
            const uint32_t kb = kk*32;
#pragma unroll
            for (int i = 0; i < MF; i++){
                ldsm4(ah[i], stA_hi + a_off + i*16*(SA*2) + kb);
                ldsm4(al[i], stA_lo + a_off + i*16*(SA*2) + kb);
            }
#pragma unroll
            for (int j2 = 0; j2 < 2; j2++){
                ldsm4(bh[j2], stB_hi + b_off + j2*16*(SA*2) + kb);
                ldsm4(bl[j2], stB_lo + b_off + j2*16*(SA*2) + kb);
            }
#pragma unroll
            for (int i = 0; i < MF; i++)
#pragma unroll
                for (int j = 0; j < 4; j++){
                    const uint32_t* Bh2 = &bh[j >> 1][(j & 1)*2];
                    const uint32_t* Bl2 = &bl[j >> 1][(j & 1)*2];
                    mma16816(acc[i][j], ah[i], Bh2);
                    mma16816(acc[i][j], ah[i], Bl2);
                    mma16816(acc[i][j], al[i], Bh2);
                }
        }
        __syncthreads();
    }

    // ---- epilogue: regs -> swizzled fp32 smem tile -> coalesced stores ----
    float* ft = (float*)smem;
    const int q = lane >> 2, nn0 = (lane & 3)*2;
#pragma unroll
    for (int i = 0; i < MF; i++)
#pragma unroll
        for (int j = 0; j < 4; j++){
            int n = wn + j*8 + nn0;
            int C4 = n >> 2, half = (n >> 1) & 1;
            int r0 = wm + i*16 + q, r1 = r0 + 8;
            *(float2*)&ft[r0*BN + ((C4 ^ (r0 & 7)) << 2) + half*2] =
                make_float2(acc[i][j][0], acc[i][j][1]);
            *(float2*)&ft[r1*BN + ((C4 ^ (r1 & 7)) << 2) + half*2] =
                make_float2(acc[i][j][2], acc[i][j][3]);
        }
    __syncthreads();

    const long long offC = zb*sCb + zh*sCh;
    constexpr int RW = BN / 4;
    constexpr int ITER = 128 * RW / 256;
#pragma unroll
    for (int i = 0; i < ITER; i++){
        int u = i*256 + tid;
        int rr = u / RW, C4 = u % RW;
        int C4s = C4 ^ (rr & 7);
        float4 v = *(const float4*)&ft[rr*BN + C4s*4];
        const size_t co = (size_t)offC + (size_t)(m0+rr)*ldc + n0 + C4*4;
        if (OUTMODE == 0){
            *(float4*)(Cf + co) = v;
        } else if (OUTMODE == 1){
            int bi = C4*4 - rr + 127;
            v.x += bias_sm[bi];   v.y += bias_sm[bi+1];
            v.z += bias_sm[bi+2]; v.w += bias_sm[bi+3];
            *(float4*)(Cf + co) = v;
        } else {
            __nv_bfloat162 h0 = __floats2bfloat162_rn(v.x, v.y);
            __nv_bfloat162 h1 = __floats2bfloat162_rn(v.z, v.w);
            __nv_bfloat162 l0 = __floats2bfloat162_rn(v.x - __bfloat162float(h0.x),
                                                      v.y - __bfloat162float(h0.y));
            __nv_bfloat162 l1 = __floats2bfloat162_rn(v.z - __bfloat162float(h1.x),
                                                      v.w - __bfloat162float(h1.y));
            *(uint2*)(Chi + co) = make_uint2(*(uint32_t*)&h0, *(uint32_t*)&h1);
            *(uint2*)(Clo + co) = make_uint2(*(uint32_t*)&l0, *(uint32_t*)&l1);
        }
    }
}

// ---------------------------------------------------------------------------
extern "C" void kernel_launch(void* const* d_in, const int* in_sizes, int n_in,
                              void* d_out, int out_size) {
    const float* hidden = (const float*)d_in[0];
    const float* wq = (const float*)d_in[1];
    const float* wk = (const float*)d_in[2];
    const float* wv = (const float*)d_in[3];
    const float* wo = (const float*)d_in[4];
    const float* rb = (const float*)d_in[5];
    float* out  = (float*)d_out;
    float* attn = out + kOUT0;

    #define SYM(p, s) void* p; cudaGetSymbolAddress(&p, s)
    SYM(xhi, g_xhi); SYM(xlo, g_xlo);
    SYM(wqhi, g_wqhi); SYM(wqlo, g_wqlo);
    SYM(wkhi, g_wkhi); SYM(wklo, g_wklo);
    SYM(wvhi, g_wvhi); SYM(wvlo, g_wvlo);
    SYM(wohi, g_wohi); SYM(wolo, g_wolo);
    SYM(qhi, g_qhi); SYM(qlo, g_qlo);
    SYM(khi, g_khi); SYM(klo, g_klo);
    SYM(vhi, g_vhi); SYM(vlo, g_vlo);
    SYM(vthi, g_vthi); SYM(vtlo, g_vtlo);
    SYM(chi, g_chi); SYM(clo, g_clo);
    #undef SYM
    typedef const __nv_bfloat16* BF;
    typedef __nv_bfloat16* BFm;

    auto proj = gemm3_kernel<128, false, 2>;
    auto qkg  = gemm3_kernel<128, false, 1>;
    auto pvg  = gemm3_kernel<64,  true,  2>;
    auto outg = gemm3_kernel<128, false, 0>;
    // BN=128: stage 40960, x2 = 81920 (epilogue 64KB fits). BN=64: 30720x2 = 61440.
    cudaFuncSetAttribute(proj, cudaFuncAttributeMaxDynamicSharedMemorySize, 81920);
    cudaFuncSetAttribute(qkg,  cudaFuncAttributeMaxDynamicSharedMemorySize, 81920);
    cudaFuncSetAttribute(outg, cudaFuncAttributeMaxDynamicSharedMemorySize, 81920);
    cudaFuncSetAttribute(pvg,  cudaFuncAttributeMaxDynamicSharedMemorySize, 61440);

    bias_kernel<<<(kH*kNB + 255)/256, 256>>>(rb);
    convert_x_kernel<<<kM*kD/256, 256>>>(hidden);
    dim3 tb(32, 8);
    transpose_split_kernel<<<dim3(32, 32), tb>>>(wq, (BFm)wqhi, (BFm)wqlo);
    transpose_split_kernel<<<dim3(32, 32), tb>>>(wk, (BFm)wkhi, (BFm)wklo);
    transpose_split_kernel<<<dim3(32, 32), tb>>>(wv, (BFm)wvhi, (BFm)wvlo);
    transpose_split_kernel<<<dim3(32, 32), tb>>>(wo, (BFm)wohi, (BFm)wolo);

    proj<<<dim3(8, 32, 1), 256, 81920>>>(
        (BF)xhi, (BF)xlo, nullptr, kD, 0, 0,
        (BF)wqhi, (BF)wqlo, kD, 0, 0,
        nullptr, (BFm)qhi, (BFm)qlo, kD, 0, 0, kD);
    proj<<<dim3(8, 32, 1), 256, 81920>>>(
        (BF)xhi, (BF)xlo, nullptr, kD, 0, 0,
        (BF)wkhi, (BF)wklo, kD, 0, 0,
        nullptr, (BFm)khi, (BFm)klo, kD, 0, 0, kD);
    proj<<<dim3(8, 32, 1), 256, 81920>>>(
        (BF)xhi, (BF)xlo, nullptr, kD, 0, 0,
        (BF)wvhi, (BF)wvlo, kD, 0, 0,
        nullptr, (BFm)vhi, (BFm)vlo, kD, 0, 0, kD);

    transpose_v_kernel<<<dim3(64, 2, 32), tb>>>();

    qkg<<<dim3(16, 16, 32), 256, 81920>>>(
        (BF)qhi, (BF)qlo, nullptr, kD, 2097152LL, 64LL,
        (BF)khi, (BF)klo, kD, 2097152LL, 64LL,
        attn, nullptr, nullptr, kS, 67108864LL, 4194304LL, kDK);

    softmax_kernel<<<kBH*kS, 256>>>(attn);

    pvg<<<dim3(1, 16, 32), 256, 61440>>>(
        nullptr, nullptr, attn, kS, 67108864LL, 4194304LL,
        (BF)vthi, (BF)vtlo, kS, 2097152LL, 131072LL,
        nullptr, (BFm)chi, (BFm)clo, kD, 2097152LL, 64LL, kS);

    outg<<<dim3(8, 32, 1), 256, 81920>>>(
        (BF)chi, (BF)clo, nullptr, kD, 0, 0,
        (BF)wohi, (BF)wolo, kD, 0, 0,
        out, nullptr, nullptr, kD, 0, 0, kD);
}